// round 5
// baseline (speedup 1.0000x reference)
#include <cuda_runtime.h>
#include <math.h>

// Problem constants
#define BB  2
#define TT  1024
#define DD  1024
#define HH  16
#define HDD 64
#define LL  3
#define VV  32000
#define FFD 4096
#define BT  (BB*TT)

#define BM 128
#define BN 128
#define BK 16
#define BSLD 140   // Bs row pitch (words): reads conflict-free (12k+n distinct)

// ---------------- static scratch (allocation-free) ----------------
__device__ float g_x   [BT*DD];
__device__ float g_h   [BT*DD];
__device__ float g_qkv [BT*3*DD];
__device__ float g_attn[BT*DD];
__device__ float g_sa  [BT*DD];
__device__ float g_ff1 [(size_t)BT*FFD];
__device__ float g_ff2 [BT*DD];
__device__ float g_wqkv[(size_t)LL*DD*3*DD];
__device__ float g_scores[(size_t)BB*HH*TT*TT];   // 128 MB

// ---------------- helpers ----------------
__device__ __forceinline__ unsigned f2tf32(float x) {
    unsigned r;
    asm("cvt.rna.tf32.f32 %0, %1;" : "=r"(r) : "f"(x));
    return r;
}

__device__ __forceinline__ void mma_tf32(float* c, const unsigned* a, const unsigned* b) {
    asm volatile(
        "mma.sync.aligned.m16n8k8.row.col.f32.tf32.tf32.f32 "
        "{%0,%1,%2,%3},{%4,%5,%6,%7},{%8,%9},{%0,%1,%2,%3};"
        : "+f"(c[0]), "+f"(c[1]), "+f"(c[2]), "+f"(c[3])
        : "r"(a[0]), "r"(a[1]), "r"(a[2]), "r"(a[3]), "r"(b[0]), "r"(b[1]));
}

// swizzled As index: m-row, k-group (4-word), k-low. phys group = kg ^ ((m>>1)&3)
__device__ __forceinline__ int a_idx(int m, int kg, int kl) {
    return m * 16 + (((kg) ^ ((m >> 1) & 3)) << 2) + kl;
}

// ---------------- embedding ----------------
__global__ void embed_kernel(const int* __restrict__ idx,
                             const float* __restrict__ tok,
                             const float* __restrict__ pos) {
    int bt = blockIdx.x;
    long long row = (long long)idx[bt];
    int t = bt % TT;
    const float* te = tok + row * DD;
    const float* pe = pos + (long long)t * DD;
    float* xo = g_x + (long long)bt * DD;
    for (int d = threadIdx.x; d < DD; d += blockDim.x)
        xo[d] = te[d] + pe[d];
}

// ---------------- pack wq/wk/wv -> [L][D][3D] ----------------
__global__ void pack_kernel(const float* __restrict__ wq,
                            const float* __restrict__ wk,
                            const float* __restrict__ wv) {
    const long long total = (long long)LL * DD * 3 * DD;
    for (long long j = (long long)blockIdx.x * blockDim.x + threadIdx.x;
         j < total; j += (long long)gridDim.x * blockDim.x) {
        int l = (int)(j / ((long long)DD * 3 * DD));
        long long r = j % ((long long)DD * 3 * DD);
        int d = (int)(r / (3 * DD));
        int c = (int)(r % (3 * DD));
        int m = c / DD;
        int c2 = c % DD;
        int h = c2 / HDD;
        int k = c2 % HDD;
        const float* src = (m == 0) ? wq : ((m == 1) ? wk : wv);
        g_wqkv[j] = src[((long long)l * HH + h) * DD * HDD + (long long)d * HDD + k];
    }
}

// ---------------- layernorm ----------------
__global__ void ln_kernel(const float* __restrict__ in,
                          const float* __restrict__ g,
                          const float* __restrict__ b,
                          float* __restrict__ out) {
    int row = blockIdx.x;
    const float* x = in + (long long)row * DD;
    __shared__ float rs[256];
    __shared__ float rs2[256];
    float s = 0.f, s2 = 0.f;
    for (int d = threadIdx.x; d < DD; d += 256) {
        float v = x[d];
        s += v; s2 += v * v;
    }
    rs[threadIdx.x] = s; rs2[threadIdx.x] = s2;
    __syncthreads();
    for (int o = 128; o > 0; o >>= 1) {
        if (threadIdx.x < o) { rs[threadIdx.x] += rs[threadIdx.x + o]; rs2[threadIdx.x] += rs2[threadIdx.x + o]; }
        __syncthreads();
    }
    float mean = rs[0] * (1.0f / DD);
    float var  = rs2[0] * (1.0f / DD) - mean * mean;
    float rstd = rsqrtf(var + 1e-5f);
    float* o = out + (long long)row * DD;
    for (int d = threadIdx.x; d < DD; d += 256)
        o[d] = (x[d] - mean) * rstd * g[d] + b[d];
}

// ---------------- causal scaled softmax (clipped to live region) ----------------
__global__ void softmax_kernel() {
    int r = blockIdx.x;
    int t = r % TT;
    float* row = g_scores + (long long)r * TT;
    __shared__ float red[256];
    const float scale = 0.125f;
    const int wlim = ((t >> 7) + 1) << 7;  // PV reads s < wlim only
    float vals[4];
    float mx = -1e30f;
    #pragma unroll
    for (int i = 0; i < 4; i++) {
        int s = threadIdx.x + i * 256;
        float v = (s <= t) ? row[s] * scale : -1e30f;
        vals[i] = v;
        mx = fmaxf(mx, v);
    }
    red[threadIdx.x] = mx; __syncthreads();
    for (int o = 128; o > 0; o >>= 1) {
        if (threadIdx.x < o) red[threadIdx.x] = fmaxf(red[threadIdx.x], red[threadIdx.x + o]);
        __syncthreads();
    }
    float m = red[0];
    __syncthreads();
    float sum = 0.f;
    #pragma unroll
    for (int i = 0; i < 4; i++) {
        float e = expf(vals[i] - m);
        vals[i] = e;
        sum += e;
    }
    red[threadIdx.x] = sum; __syncthreads();
    for (int o = 128; o > 0; o >>= 1) {
        if (threadIdx.x < o) red[threadIdx.x] += red[threadIdx.x + o];
        __syncthreads();
    }
    float inv = 1.0f / red[0];
    #pragma unroll
    for (int i = 0; i < 4; i++) {
        int s = threadIdx.x + i * 256;
        if (s < wlim) row[s] = vals[i] * inv;   // masked entries write exact 0
    }
}

// ---------------- elementwise add: x = sa + ff2 ----------------
__global__ void add_kernel() {
    int n = BT * DD;
    for (int i = blockIdx.x * blockDim.x + threadIdx.x; i < n;
         i += gridDim.x * blockDim.x)
        g_x[i] = g_sa[i] + g_ff2[i];
}

// ---------------- tf32 tensor-core GEMM (128 thr, 2x2 warps of 64x64) -----
// C[M,N] = A[M,K] @ B (+bias)(+relu).
// A row-major (lda). If !TB: B row-major [K,N] (ldb). If TB: B memory [N,K].
// EPI: 0 none, 1 +bias, 2 +bias+relu.
// CSKIP: skip tiles above causal diagonal. CCLIP: clip K to bm+BM.
// Requires: M % 128 == 0, K % 16 == 0 (after clip); if TB, N % 128 == 0.
template<int EPI, bool TB, bool CSKIP, bool CCLIP>
__global__ void __launch_bounds__(128)
mma_gemm(const float* __restrict__ A, const float* __restrict__ B,
         const float* __restrict__ bias, float* __restrict__ C,
         int M, int N, int K, int lda, int ldb, int ldc,
         long long Ab, long long Ah, long long Bb, long long Bh,
         long long Cb, long long Ch, int HB) {
    __shared__ __align__(16) unsigned As[2][BM * BK];        // swizzled, no pad
    __shared__ __align__(16) unsigned Bs[2][BK][BSLD];       // padded

    const int zb = blockIdx.z / HB;
    const int zh = blockIdx.z % HB;
    A += zb * Ab + zh * Ah;
    B += zb * Bb + zh * Bh;
    C += zb * Cb + zh * Ch;

    const int bm = blockIdx.x * BM;
    const int bn = blockIdx.y * BN;
    if (CSKIP && bn >= bm + BM) return;

    const int Kend = CCLIP ? min(K, bm + BM) : K;
    const int nIter = Kend >> 4;

    const int tid  = threadIdx.x;
    const int warp = tid >> 5;
    const int lane = tid & 31;
    const int g    = lane >> 2;
    const int tig  = lane & 3;
    const int wm   = (warp & 1) * 64;
    const int wn   = (warp >> 1) * 64;

    float acc[4][8][4];
    #pragma unroll
    for (int i = 0; i < 4; i++)
        #pragma unroll
        for (int j = 0; j < 8; j++)
            #pragma unroll
            for (int q = 0; q < 4; q++) acc[i][j][q] = 0.f;

    float4 ra[4], rb[4];

    // A staging: p=0..3: row = p*32 + tid/4, colchunk = (tid%4)*4  (coalesced)
    const int a_r = tid >> 2;
    const int a_c4 = tid & 3;
    // B (!TB): p=0..3: row = p*4 + tid/32, col = (tid%32)*4  (coalesced)
    const int b_r = tid >> 5;
    const int b_c = (tid & 31) << 2;
    // B (TB): p=0..3: n = p*32 + tid/4, kchunk = (tid%4)*4
    const int t_n = tid >> 2;
    const int t_k = (tid & 3) << 2;

    auto loadA = [&](int k0) {
        #pragma unroll
        for (int p = 0; p < 4; p++) {
            int r = p * 32 + a_r;
            ra[p] = *reinterpret_cast<const float4*>(A + (long long)(bm + r) * lda + (k0 + a_c4 * 4));
        }
    };
    auto loadB = [&](int k0) {
        if (!TB) {
            #pragma unroll
            for (int p = 0; p < 4; p++) {
                int r = k0 + p * 4 + b_r;
                int c = bn + b_c;
                if (c < N)
                    rb[p] = *reinterpret_cast<const float4*>(B + (long long)r * ldb + c);
                else
                    rb[p] = make_float4(0.f, 0.f, 0.f, 0.f);
            }
        } else {
            #pragma unroll
            for (int p = 0; p < 4; p++) {
                int n = bn + p * 32 + t_n;
                rb[p] = *reinterpret_cast<const float4*>(B + (long long)n * ldb + (k0 + t_k));
            }
        }
    };
    auto storeAB = [&](int buf) {
        #pragma unroll
        for (int p = 0; p < 4; p++) {
            int m = p * 32 + a_r;
            int grp = a_c4 ^ ((m >> 1) & 3);
            uint4 v = make_uint4(f2tf32(ra[p].x), f2tf32(ra[p].y), f2tf32(ra[p].z), f2tf32(ra[p].w));
            *reinterpret_cast<uint4*>(&As[buf][m * 16 + (grp << 2)]) = v;
        }
        if (!TB) {
            #pragma unroll
            for (int p = 0; p < 4; p++) {
                int r = p * 4 + b_r;
                uint4 v = make_uint4(f2tf32(rb[p].x), f2tf32(rb[p].y), f2tf32(rb[p].z), f2tf32(rb[p].w));
                *reinterpret_cast<uint4*>(&Bs[buf][r][b_c]) = v;
            }
        } else {
            #pragma unroll
            for (int p = 0; p < 4; p++) {
                int n = p * 32 + t_n;
                Bs[buf][t_k + 0][n] = f2tf32(rb[p].x);
                Bs[buf][t_k + 1][n] = f2tf32(rb[p].y);
                Bs[buf][t_k + 2][n] = f2tf32(rb[p].z);
                Bs[buf][t_k + 3][n] = f2tf32(rb[p].w);
            }
        }
    };
    auto compute = [&](int buf) {
        #pragma unroll
        for (int ks = 0; ks < 2; ks++) {
            const int kk = ks * 8;
            const int K2 = kk >> 2;          // 0 or 2
            unsigned af[4][4];
            #pragma unroll
            for (int mi = 0; mi < 4; mi++) {
                int m0 = wm + mi * 16 + g;
                // m16n8k8.tf32 A frag: a0=(g,t) a1=(g+8,t) a2=(g,t+4) a3=(g+8,t+4)
                af[mi][0] = As[buf][a_idx(m0,     K2,     tig)];
                af[mi][1] = As[buf][a_idx(m0 + 8, K2,     tig)];
                af[mi][2] = As[buf][a_idx(m0,     K2 + 1, tig)];
                af[mi][3] = As[buf][a_idx(m0 + 8, K2 + 1, tig)];
            }
            #pragma unroll
            for (int nj = 0; nj < 8; nj++) {
                int c0 = wn + nj * 8 + g;
                unsigned bf[2];
                bf[0] = Bs[buf][kk + tig][c0];
                bf[1] = Bs[buf][kk + tig + 4][c0];
                #pragma unroll
                for (int mi = 0; mi < 4; mi++)
                    mma_tf32(acc[mi][nj], af[mi], bf);
            }
        }
    };

    loadA(0); loadB(0);
    storeAB(0);
    __syncthreads();

    for (int it = 0; it < nIter; it++) {
        int buf = it & 1;
        bool more = (it + 1 < nIter);
        if (more) { loadA((it + 1) << 4); loadB((it + 1) << 4); }
        compute(buf);
        if (more) storeAB(buf ^ 1);
        __syncthreads();
    }

    // epilogue: c0:(r,c) c1:(r,c+1) c2:(r+8,c) c3:(r+8,c+1)
    #pragma unroll
    for (int mi = 0; mi < 4; mi++) {
        int row = bm + wm + mi * 16 + g;
        #pragma unroll
        for (int nj = 0; nj < 8; nj++) {
            int col = bn + wn + nj * 8 + tig * 2;
            if (col >= N) continue;
            float v0 = acc[mi][nj][0];
            float v1 = acc[mi][nj][1];
            float v2 = acc[mi][nj][2];
            float v3 = acc[mi][nj][3];
            if (EPI >= 1) {
                float bb0 = bias[col];
                float bb1 = bias[col + 1];
                v0 += bb0; v1 += bb1; v2 += bb0; v3 += bb1;
            }
            if (EPI == 2) {
                v0 = fmaxf(v0, 0.f); v1 = fmaxf(v1, 0.f);
                v2 = fmaxf(v2, 0.f); v3 = fmaxf(v3, 0.f);
            }
            *reinterpret_cast<float2*>(C + (long long)row * ldc + col)       = make_float2(v0, v1);
            *reinterpret_cast<float2*>(C + (long long)(row + 8) * ldc + col) = make_float2(v2, v3);
        }
    }
}

// dense launcher (non-batched)
static void dense_gemm(const float* A, const float* B, const float* bias, float* C,
                       int M, int N, int K, int lda, int ldb, int ldc, int epi) {
    dim3 grid(M / BM, (N + BN - 1) / BN, 1);
    if (epi == 0)
        mma_gemm<0,false,false,false><<<grid,128>>>(A,B,bias,C,M,N,K,lda,ldb,ldc,0,0,0,0,0,0,1);
    else if (epi == 1)
        mma_gemm<1,false,false,false><<<grid,128>>>(A,B,bias,C,M,N,K,lda,ldb,ldc,0,0,0,0,0,0,1);
    else
        mma_gemm<2,false,false,false><<<grid,128>>>(A,B,bias,C,M,N,K,lda,ldb,ldc,0,0,0,0,0,0,1);
}

extern "C" void kernel_launch(void* const* d_in, const int* in_sizes, int n_in,
                              void* d_out, int out_size) {
    const int*   idx         = (const int*)d_in[0];     // int32
    const float* tok_emb     = (const float*)d_in[1];
    const float* pos_emb     = (const float*)d_in[2];
    const float* wq          = (const float*)d_in[3];
    const float* wk          = (const float*)d_in[4];
    const float* wv          = (const float*)d_in[5];
    const float* w_proj      = (const float*)d_in[6];
    const float* b_proj      = (const float*)d_in[7];
    const float* w1          = (const float*)d_in[8];
    const float* b1          = (const float*)d_in[9];
    const float* w2          = (const float*)d_in[10];
    const float* b2          = (const float*)d_in[11];
    const float* ln1_g       = (const float*)d_in[12];
    const float* ln1_b       = (const float*)d_in[13];
    const float* ln2_g       = (const float*)d_in[14];
    const float* ln2_b       = (const float*)d_in[15];
    const float* lnf_g       = (const float*)d_in[16];
    const float* lnf_b       = (const float*)d_in[17];
    const float* w_lm        = (const float*)d_in[18];
    const float* b_lm        = (const float*)d_in[19];
    float* out = (float*)d_out;

    float *px, *ph, *pqkv, *pattn, *psa, *pff1, *pff2, *pwqkv, *pscores;
    cudaGetSymbolAddress((void**)&px,     g_x);
    cudaGetSymbolAddress((void**)&ph,     g_h);
    cudaGetSymbolAddress((void**)&pqkv,   g_qkv);
    cudaGetSymbolAddress((void**)&pattn,  g_attn);
    cudaGetSymbolAddress((void**)&psa,    g_sa);
    cudaGetSymbolAddress((void**)&pff1,   g_ff1);
    cudaGetSymbolAddress((void**)&pff2,   g_ff2);
    cudaGetSymbolAddress((void**)&pwqkv,  g_wqkv);
    cudaGetSymbolAddress((void**)&pscores,g_scores);

    pack_kernel<<<4096, 256>>>(wq, wk, wv);
    embed_kernel<<<BT, 256>>>(idx, tok_emb, pos_emb);

    const long long TT2 = (long long)TT * TT;

    for (int l = 0; l < LL; l++) {
        ln_kernel<<<BT, 256>>>(px, ln1_g + (long long)l*DD, ln1_b + (long long)l*DD, ph);

        // fused QKV
        dense_gemm(ph, pwqkv + (long long)l*DD*3*DD, nullptr, pqkv,
                   BT, 3*DD, DD, DD, 3*DD, 3*DD, 0);

        // scores = Q @ K^T, batched over B*H, causal tiles skipped
        {
            dim3 grid(TT/BM, TT/BN, BB*HH);
            mma_gemm<0,true,true,false><<<grid,128>>>(
                pqkv,              // Q
                pqkv + DD,         // K (memory [t,k] -> TB)
                nullptr, pscores,
                TT, TT, HDD,
                3*DD, 3*DD, TT,
                (long long)TT*3*DD, HDD,
                (long long)TT*3*DD, HDD,
                (long long)HH*TT2, TT2,
                HH);
        }

        softmax_kernel<<<BB*HH*TT, 256>>>();

        // attn = P @ V, batched, K clipped to causal extent
        {
            dim3 grid(TT/BM, 1, BB*HH);
            mma_gemm<0,false,false,true><<<grid,128>>>(
                pscores,
                pqkv + 2*DD,       // V
                nullptr, pattn,
                TT, HDD, TT,
                TT, 3*DD, DD,
                (long long)HH*TT2, TT2,
                (long long)TT*3*DD, HDD,
                (long long)TT*DD, HDD,
                HH);
        }

        // sa = attn @ w_proj + b_proj
        dense_gemm(pattn, w_proj + (long long)l*DD*DD, b_proj + (long long)l*DD, psa,
                   BT, DD, DD, DD, DD, DD, 1);

        ln_kernel<<<BT, 256>>>(px, ln2_g + (long long)l*DD, ln2_b + (long long)l*DD, ph);

        // ff1 = relu(h @ w1 + b1)
        dense_gemm(ph, w1 + (long long)l*DD*FFD, b1 + (long long)l*FFD, pff1,
                   BT, FFD, DD, DD, FFD, FFD, 2);

        // ff2 = ff1 @ w2 + b2
        dense_gemm(pff1, w2 + (long long)l*FFD*DD, b2 + (long long)l*DD, pff2,
                   BT, DD, FFD, FFD, DD, DD, 1);

        add_kernel<<<2048, 256>>>();
    }

    ln_kernel<<<BT, 256>>>(px, lnf_g, lnf_b, ph);

    // logits = h @ w_lm + b_lm
    dense_gemm(ph, w_lm, b_lm, out, BT, VV, DD, DD, VV, VV, 1);
}

// round 6
// speedup vs baseline: 1.3745x; 1.3745x over previous
#include <cuda_runtime.h>
#include <math.h>

// Problem constants
#define BB  2
#define TT  1024
#define DD  1024
#define HH  16
#define HDD 64
#define LL  3
#define VV  32000
#define FFD 4096
#define BT  (BB*TT)

#define BM 128
#define BN 128
#define BK 16
#define BSLD 140        // dense Bs row pitch (words) - conflict-free reads
#define TBLD 20         // TB Bs row pitch (words)
#define BSWORDS 2560    // max(16*140, 128*20)

// ---------------- static scratch (allocation-free) ----------------
__device__ float g_x   [BT*DD];
__device__ float g_h   [BT*DD];
__device__ float g_qkv [BT*3*DD];
__device__ float g_attn[BT*DD];
__device__ float g_sa  [BT*DD];
__device__ float g_ff1 [(size_t)BT*FFD];
__device__ float g_ff2 [BT*DD];
__device__ float g_wqkv[(size_t)LL*DD*3*DD];
__device__ float g_scores[(size_t)BB*HH*TT*TT];   // 128 MB
// tf32-rounded weight copies
__device__ float g_wproj_r[(size_t)LL*DD*DD];
__device__ float g_w1_r  [(size_t)LL*DD*FFD];
__device__ float g_w2_r  [(size_t)LL*FFD*DD];
__device__ float g_wlm_r [(size_t)DD*VV];

// ---------------- helpers ----------------
__device__ __forceinline__ unsigned f2tf32(float x) {
    unsigned r;
    asm("cvt.rna.tf32.f32 %0, %1;" : "=r"(r) : "f"(x));
    return r;
}
__device__ __forceinline__ float roundtf(float x) {
    return __uint_as_float(f2tf32(x));
}

__device__ __forceinline__ void mma_tf32(float* c, const unsigned* a, const unsigned* b) {
    asm volatile(
        "mma.sync.aligned.m16n8k8.row.col.f32.tf32.tf32.f32 "
        "{%0,%1,%2,%3},{%4,%5,%6,%7},{%8,%9},{%0,%1,%2,%3};"
        : "+f"(c[0]), "+f"(c[1]), "+f"(c[2]), "+f"(c[3])
        : "r"(a[0]), "r"(a[1]), "r"(a[2]), "r"(a[3]), "r"(b[0]), "r"(b[1]));
}

// swizzled As word index: phys group = kg ^ ((m>>1)&3)
__device__ __forceinline__ int a_idx(int m, int kg, int kl) {
    return m * 16 + (((kg) ^ ((m >> 1) & 3)) << 2) + kl;
}

__device__ __forceinline__ void cp16(unsigned dst, const float* src, int szbytes) {
    asm volatile("cp.async.cg.shared.global [%0], [%1], 16, %2;"
                 :: "r"(dst), "l"(src), "r"(szbytes));
}
__device__ __forceinline__ void cp_commit() {
    asm volatile("cp.async.commit_group;");
}
template<int N>
__device__ __forceinline__ void cp_wait() {
    asm volatile("cp.async.wait_group %0;" :: "n"(N));
}

// ---------------- embedding ----------------
__global__ void embed_kernel(const int* __restrict__ idx,
                             const float* __restrict__ tok,
                             const float* __restrict__ pos) {
    int bt = blockIdx.x;
    long long row = (long long)idx[bt];
    int t = bt % TT;
    const float* te = tok + row * DD;
    const float* pe = pos + (long long)t * DD;
    float* xo = g_x + (long long)bt * DD;
    for (int d = threadIdx.x; d < DD; d += blockDim.x)
        xo[d] = te[d] + pe[d];
}

// ---------------- pack wq/wk/wv -> [L][D][3D], tf32-rounded ----------------
__global__ void pack_kernel(const float* __restrict__ wq,
                            const float* __restrict__ wk,
                            const float* __restrict__ wv) {
    const long long total = (long long)LL * DD * 3 * DD;
    for (long long j = (long long)blockIdx.x * blockDim.x + threadIdx.x;
         j < total; j += (long long)gridDim.x * blockDim.x) {
        int l = (int)(j / ((long long)DD * 3 * DD));
        long long r = j % ((long long)DD * 3 * DD);
        int d = (int)(r / (3 * DD));
        int c = (int)(r % (3 * DD));
        int m = c / DD;
        int c2 = c % DD;
        int h = c2 / HDD;
        int k = c2 % HDD;
        const float* src = (m == 0) ? wq : ((m == 1) ? wk : wv);
        g_wqkv[j] = roundtf(src[((long long)l * HH + h) * DD * HDD + (long long)d * HDD + k]);
    }
}

// ---------------- tf32 round-copy for weights ----------------
__global__ void round_copy(const float* __restrict__ src, float* __restrict__ dst,
                           long long n4) {
    for (long long i = (long long)blockIdx.x * blockDim.x + threadIdx.x;
         i < n4; i += (long long)gridDim.x * blockDim.x) {
        float4 v = reinterpret_cast<const float4*>(src)[i];
        v.x = roundtf(v.x); v.y = roundtf(v.y); v.z = roundtf(v.z); v.w = roundtf(v.w);
        reinterpret_cast<float4*>(dst)[i] = v;
    }
}

// ---------------- layernorm (tf32-rounded output) ----------------
__global__ void ln_kernel(const float* __restrict__ in,
                          const float* __restrict__ g,
                          const float* __restrict__ b,
                          float* __restrict__ out) {
    int row = blockIdx.x;
    const float* x = in + (long long)row * DD;
    __shared__ float rs[256];
    __shared__ float rs2[256];
    float s = 0.f, s2 = 0.f;
    for (int d = threadIdx.x; d < DD; d += 256) {
        float v = x[d];
        s += v; s2 += v * v;
    }
    rs[threadIdx.x] = s; rs2[threadIdx.x] = s2;
    __syncthreads();
    for (int o = 128; o > 0; o >>= 1) {
        if (threadIdx.x < o) { rs[threadIdx.x] += rs[threadIdx.x + o]; rs2[threadIdx.x] += rs2[threadIdx.x + o]; }
        __syncthreads();
    }
    float mean = rs[0] * (1.0f / DD);
    float var  = rs2[0] * (1.0f / DD) - mean * mean;
    float rstd = rsqrtf(var + 1e-5f);
    float* o = out + (long long)row * DD;
    for (int d = threadIdx.x; d < DD; d += 256)
        o[d] = roundtf((x[d] - mean) * rstd * g[d] + b[d]);
}

// ---------------- causal scaled softmax (clipped, tf32-rounded) ----------------
__global__ void softmax_kernel() {
    int r = blockIdx.x;
    int t = r % TT;
    float* row = g_scores + (long long)r * TT;
    __shared__ float red[256];
    const float scale = 0.125f;
    const int wlim = ((t >> 7) + 1) << 7;  // PV reads s < wlim only
    float vals[4];
    float mx = -1e30f;
    #pragma unroll
    for (int i = 0; i < 4; i++) {
        int s = threadIdx.x + i * 256;
        float v = (s <= t) ? row[s] * scale : -1e30f;
        vals[i] = v;
        mx = fmaxf(mx, v);
    }
    red[threadIdx.x] = mx; __syncthreads();
    for (int o = 128; o > 0; o >>= 1) {
        if (threadIdx.x < o) red[threadIdx.x] = fmaxf(red[threadIdx.x], red[threadIdx.x + o]);
        __syncthreads();
    }
    float m = red[0];
    __syncthreads();
    float sum = 0.f;
    #pragma unroll
    for (int i = 0; i < 4; i++) {
        float e = expf(vals[i] - m);
        vals[i] = e;
        sum += e;
    }
    red[threadIdx.x] = sum; __syncthreads();
    for (int o = 128; o > 0; o >>= 1) {
        if (threadIdx.x < o) red[threadIdx.x] += red[threadIdx.x + o];
        __syncthreads();
    }
    float inv = 1.0f / red[0];
    #pragma unroll
    for (int i = 0; i < 4; i++) {
        int s = threadIdx.x + i * 256;
        if (s < wlim) row[s] = roundtf(vals[i] * inv);
    }
}

// ---------------- elementwise add: x = sa + ff2 ----------------
__global__ void add_kernel() {
    int n = BT * DD;
    for (int i = blockIdx.x * blockDim.x + threadIdx.x; i < n;
         i += gridDim.x * blockDim.x)
        g_x[i] = g_sa[i] + g_ff2[i];
}

// ---------------- tf32 tensor-core GEMM, cp.async pipelined ----------------
// Inputs MUST be tf32-pre-rounded fp32. 128 thr, 2x2 warps of 64x64.
// EPI: 0 none, 1 +bias, 2 +bias+relu.  RND: tf32-round outputs.
// TB: B memory [N,K].  CSKIP: causal tile skip.  CCLIP: clip K to bm+BM.
template<int EPI, bool RND, bool TB, bool CSKIP, bool CCLIP>
__global__ void __launch_bounds__(128, 2)
mma_gemm(const float* __restrict__ A, const float* __restrict__ B,
         const float* __restrict__ bias, float* __restrict__ C,
         int M, int N, int K, int lda, int ldb, int ldc,
         long long Ab, long long Ah, long long Bb, long long Bh,
         long long Cb, long long Ch, int HB) {
    __shared__ __align__(16) unsigned As[2][BM * BK];
    __shared__ __align__(16) unsigned Bs[2][BSWORDS];

    const int zb = blockIdx.z / HB;
    const int zh = blockIdx.z % HB;
    A += zb * Ab + zh * Ah;
    B += zb * Bb + zh * Bh;
    C += zb * Cb + zh * Ch;

    const int bm = blockIdx.x * BM;
    const int bn = blockIdx.y * BN;
    if (CSKIP && bn >= bm + BM) return;

    const int Kend = CCLIP ? min(K, bm + BM) : K;
    const int nIter = Kend >> 4;

    const int tid  = threadIdx.x;
    const int warp = tid >> 5;
    const int lane = tid & 31;
    const int g    = lane >> 2;
    const int tig  = lane & 3;
    const int wm   = (warp & 1) * 64;
    const int wn   = (warp >> 1) * 64;

    const unsigned sA = (unsigned)__cvta_generic_to_shared(&As[0][0]);
    const unsigned sB = (unsigned)__cvta_generic_to_shared(&Bs[0][0]);

    // load-thread mapping
    const int a_r  = tid >> 2;          // 0..31
    const int a_c4 = tid & 3;           // k chunk
    const int b_r  = tid >> 5;          // 0..3 (dense)
    const int b_c  = (tid & 31) << 2;   // 0..124 (dense)
    const int t_n  = tid >> 2;          // 0..31 (TB)
    const int t_k  = (tid & 3) << 2;    // 0..12 (TB)

    auto issueLoads = [&](int stage, int k0) {
        #pragma unroll
        for (int p = 0; p < 4; p++) {
            int m = p * 32 + a_r;
            int grp = a_c4 ^ ((m >> 1) & 3);
            unsigned dst = sA + (unsigned)((stage * BM * BK + m * 16 + grp * 4) * 4);
            cp16(dst, A + (long long)(bm + m) * lda + (k0 + a_c4 * 4), 16);
        }
        if (!TB) {
            #pragma unroll
            for (int p = 0; p < 4; p++) {
                int r = k0 + p * 4 + b_r;
                int c = bn + b_c;
                unsigned dst = sB + (unsigned)((stage * BSWORDS + (p * 4 + b_r) * BSLD + b_c) * 4);
                const float* sp = B + (long long)r * ldb + (c < N ? c : 0);
                cp16(dst, sp, (c < N) ? 16 : 0);
            }
        } else {
            #pragma unroll
            for (int p = 0; p < 4; p++) {
                int n = p * 32 + t_n;
                unsigned dst = sB + (unsigned)((stage * BSWORDS + n * TBLD + t_k) * 4);
                cp16(dst, B + (long long)(bn + n) * ldb + (k0 + t_k), 16);
            }
        }
    };

    float acc[4][8][4];
    #pragma unroll
    for (int i = 0; i < 4; i++)
        #pragma unroll
        for (int j = 0; j < 8; j++)
            #pragma unroll
            for (int q = 0; q < 4; q++) acc[i][j][q] = 0.f;

    auto loadAfrag = [&](int buf, int ks, unsigned (*af)[4]) {
        #pragma unroll
        for (int mi = 0; mi < 4; mi++) {
            int m0 = wm + mi * 16 + g;
            af[mi][0] = As[buf][a_idx(m0,     ks * 2,     tig)];
            af[mi][1] = As[buf][a_idx(m0 + 8, ks * 2,     tig)];
            af[mi][2] = As[buf][a_idx(m0,     ks * 2 + 1, tig)];
            af[mi][3] = As[buf][a_idx(m0 + 8, ks * 2 + 1, tig)];
        }
    };
    auto loadBfrag = [&](int buf, int ks, int nj, unsigned& b0, unsigned& b1) {
        int c0 = wn + nj * 8 + g;
        if (TB) {
            b0 = Bs[buf][c0 * TBLD + ks * 8 + tig];
            b1 = Bs[buf][c0 * TBLD + ks * 8 + tig + 4];
        } else {
            b0 = Bs[buf][(ks * 8 + tig) * BSLD + c0];
            b1 = Bs[buf][(ks * 8 + tig + 4) * BSLD + c0];
        }
    };

    issueLoads(0, 0);
    cp_commit();

    unsigned af[2][4][4];

    for (int it = 0; it < nIter; it++) {
        int buf = it & 1;
        if (it + 1 < nIter) {
            issueLoads(buf ^ 1, (it + 1) << 4);
            cp_commit();
            cp_wait<1>();
        } else {
            cp_wait<0>();
        }
        __syncthreads();

        loadAfrag(buf, 0, af[0]);
        #pragma unroll
        for (int ks = 0; ks < 2; ks++) {
            if (ks == 0) loadAfrag(buf, 1, af[1]);
            unsigned bc0, bc1, bn0, bn1;
            loadBfrag(buf, ks, 0, bc0, bc1);
            #pragma unroll
            for (int nj = 0; nj < 8; nj++) {
                if (nj < 7) loadBfrag(buf, ks, nj + 1, bn0, bn1);
                unsigned bb[2] = {bc0, bc1};
                #pragma unroll
                for (int mi = 0; mi < 4; mi++)
                    mma_tf32(acc[mi][nj], af[ks][mi], bb);
                bc0 = bn0; bc1 = bn1;
            }
        }
        __syncthreads();
    }

    // epilogue: c0:(r,c) c1:(r,c+1) c2:(r+8,c) c3:(r+8,c+1)
    #pragma unroll
    for (int mi = 0; mi < 4; mi++) {
        int row = bm + wm + mi * 16 + g;
        #pragma unroll
        for (int nj = 0; nj < 8; nj++) {
            int col = bn + wn + nj * 8 + tig * 2;
            if (col >= N) continue;
            float v0 = acc[mi][nj][0];
            float v1 = acc[mi][nj][1];
            float v2 = acc[mi][nj][2];
            float v3 = acc[mi][nj][3];
            if (EPI >= 1) {
                float bb0 = bias[col];
                float bb1 = bias[col + 1];
                v0 += bb0; v1 += bb1; v2 += bb0; v3 += bb1;
            }
            if (EPI == 2) {
                v0 = fmaxf(v0, 0.f); v1 = fmaxf(v1, 0.f);
                v2 = fmaxf(v2, 0.f); v3 = fmaxf(v3, 0.f);
            }
            if (RND) {
                v0 = roundtf(v0); v1 = roundtf(v1);
                v2 = roundtf(v2); v3 = roundtf(v3);
            }
            *reinterpret_cast<float2*>(C + (long long)row * ldc + col)       = make_float2(v0, v1);
            *reinterpret_cast<float2*>(C + (long long)(row + 8) * ldc + col) = make_float2(v2, v3);
        }
    }
}

extern "C" void kernel_launch(void* const* d_in, const int* in_sizes, int n_in,
                              void* d_out, int out_size) {
    const int*   idx         = (const int*)d_in[0];     // int32
    const float* tok_emb     = (const float*)d_in[1];
    const float* pos_emb     = (const float*)d_in[2];
    const float* wq          = (const float*)d_in[3];
    const float* wk          = (const float*)d_in[4];
    const float* wv          = (const float*)d_in[5];
    const float* w_proj      = (const float*)d_in[6];
    const float* b_proj      = (const float*)d_in[7];
    const float* w1          = (const float*)d_in[8];
    const float* b1          = (const float*)d_in[9];
    const float* w2          = (const float*)d_in[10];
    const float* b2          = (const float*)d_in[11];
    const float* ln1_g       = (const float*)d_in[12];
    const float* ln1_b       = (const float*)d_in[13];
    const float* ln2_g       = (const float*)d_in[14];
    const float* ln2_b       = (const float*)d_in[15];
    const float* lnf_g       = (const float*)d_in[16];
    const float* lnf_b       = (const float*)d_in[17];
    const float* w_lm        = (const float*)d_in[18];
    const float* b_lm        = (const float*)d_in[19];
    float* out = (float*)d_out;

    float *px, *ph, *pqkv, *pattn, *psa, *pff1, *pff2, *pwqkv, *pscores;
    float *pwproj, *pw1, *pw2, *pwlm;
    cudaGetSymbolAddress((void**)&px,     g_x);
    cudaGetSymbolAddress((void**)&ph,     g_h);
    cudaGetSymbolAddress((void**)&pqkv,   g_qkv);
    cudaGetSymbolAddress((void**)&pattn,  g_attn);
    cudaGetSymbolAddress((void**)&psa,    g_sa);
    cudaGetSymbolAddress((void**)&pff1,   g_ff1);
    cudaGetSymbolAddress((void**)&pff2,   g_ff2);
    cudaGetSymbolAddress((void**)&pwqkv,  g_wqkv);
    cudaGetSymbolAddress((void**)&pscores,g_scores);
    cudaGetSymbolAddress((void**)&pwproj, g_wproj_r);
    cudaGetSymbolAddress((void**)&pw1,    g_w1_r);
    cudaGetSymbolAddress((void**)&pw2,    g_w2_r);
    cudaGetSymbolAddress((void**)&pwlm,   g_wlm_r);

    // weight prep (tf32 pre-round) + embeddings
    pack_kernel<<<4096, 256>>>(wq, wk, wv);
    round_copy<<<2048, 256>>>(w_proj, pwproj, (long long)LL*DD*DD/4);
    round_copy<<<4096, 256>>>(w1, pw1, (long long)LL*DD*FFD/4);
    round_copy<<<4096, 256>>>(w2, pw2, (long long)LL*FFD*DD/4);
    round_copy<<<8192, 256>>>(w_lm, pwlm, (long long)DD*VV/4);
    embed_kernel<<<BT, 256>>>(idx, tok_emb, pos_emb);

    const long long TT2 = (long long)TT * TT;

    for (int l = 0; l < LL; l++) {
        ln_kernel<<<BT, 256>>>(px, ln1_g + (long long)l*DD, ln1_b + (long long)l*DD, ph);

        // fused QKV (outputs rounded: Q,K,V feed MMAs)
        {
            dim3 grid(BT/BM, 3*DD/BN, 1);
            mma_gemm<0,true,false,false,false><<<grid,128>>>(
                ph, pwqkv + (long long)l*DD*3*DD, nullptr, pqkv,
                BT, 3*DD, DD, DD, 3*DD, 3*DD, 0,0,0,0,0,0, 1);
        }

        // scores = Q @ K^T, batched over B*H, causal tiles skipped
        {
            dim3 grid(TT/BM, TT/BN, BB*HH);
            mma_gemm<0,false,true,true,false><<<grid,128>>>(
                pqkv, pqkv + DD, nullptr, pscores,
                TT, TT, HDD,
                3*DD, 3*DD, TT,
                (long long)TT*3*DD, HDD,
                (long long)TT*3*DD, HDD,
                (long long)HH*TT2, TT2,
                HH);
        }

        softmax_kernel<<<BB*HH*TT, 256>>>();

        // attn = P @ V, batched, K clipped (outputs rounded: feeds proj)
        {
            dim3 grid(TT/BM, 1, BB*HH);
            mma_gemm<0,true,false,false,true><<<grid,128>>>(
                pscores, pqkv + 2*DD, nullptr, pattn,
                TT, HDD, TT,
                TT, 3*DD, DD,
                (long long)HH*TT2, TT2,
                (long long)TT*3*DD, HDD,
                (long long)TT*DD, HDD,
                HH);
        }

        // sa = attn @ w_proj + b_proj (fp32 out, feeds add)
        {
            dim3 grid(BT/BM, DD/BN, 1);
            mma_gemm<1,false,false,false,false><<<grid,128>>>(
                pattn, pwproj + (long long)l*DD*DD, b_proj + (long long)l*DD, psa,
                BT, DD, DD, DD, DD, DD, 0,0,0,0,0,0, 1);
        }

        ln_kernel<<<BT, 256>>>(px, ln2_g + (long long)l*DD, ln2_b + (long long)l*DD, ph);

        // ff1 = relu(h @ w1 + b1) (rounded: feeds ff2 GEMM)
        {
            dim3 grid(BT/BM, FFD/BN, 1);
            mma_gemm<2,true,false,false,false><<<grid,128>>>(
                ph, pw1 + (long long)l*DD*FFD, b1 + (long long)l*FFD, pff1,
                BT, FFD, DD, DD, FFD, FFD, 0,0,0,0,0,0, 1);
        }

        // ff2 = ff1 @ w2 + b2 (fp32 out)
        {
            dim3 grid(BT/BM, DD/BN, 1);
            mma_gemm<1,false,false,false,false><<<grid,128>>>(
                pff1, pw2 + (long long)l*FFD*DD, b2 + (long long)l*DD, pff2,
                BT, DD, FFD, FFD, DD, DD, 0,0,0,0,0,0, 1);
        }

        add_kernel<<<2048, 256>>>();
    }

    ln_kernel<<<BT, 256>>>(px, lnf_g, lnf_b, ph);

    // logits = h @ w_lm + b_lm
    {
        dim3 grid(BT/BM, VV/BN, 1);
        mma_gemm<1,false,false,false,false><<<grid,128>>>(
            ph, pwlm, b_lm, out,
            BT, VV, DD, DD, VV, VV, 0,0,0,0,0,0, 1);
    }
}

// round 7
// speedup vs baseline: 2.2035x; 1.6031x over previous
#include <cuda_runtime.h>
#include <cuda_fp16.h>
#include <math.h>

// Problem constants
#define BB  2
#define TT  1024
#define DD  1024
#define HH  16
#define HDD 64
#define LL  3
#define VV  32000
#define FFD 4096
#define BT  (BB*TT)

#define BM 128
#define BN 128
#define BK 32

// ---------------- static scratch (allocation-free) ----------------
__device__ float  g_x   [BT*DD];                       // fp32 residual stream
__device__ __half g_h   [BT*DD];                       // LN output
__device__ __half g_qkv [BT*3*DD];
__device__ __half g_attn[BT*DD];
__device__ float  g_sa  [BT*DD];
__device__ __half g_ff1 [(size_t)BT*FFD];
__device__ float  g_ff2 [BT*DD];
__device__ float  g_scores[(size_t)BB*HH*TT*TT];       // 128 MB fp32
__device__ __half g_p   [(size_t)BB*HH*TT*TT];         // softmax probs fp16
__device__ __half g_vT  [(size_t)BB*HH*128*TT];        // V transposed, padded to 128 rows
// fp16 transposed weights
__device__ __half g_wqkvT [(size_t)LL*3*DD*DD];        // [l][n=3D][k=D]
__device__ __half g_wprojT[(size_t)LL*DD*DD];
__device__ __half g_w1T   [(size_t)LL*FFD*DD];
__device__ __half g_w2T   [(size_t)LL*DD*FFD];
__device__ __half g_wlmT  [(size_t)VV*DD];

// ---------------- helpers ----------------
__device__ __forceinline__ void mma_f16(float* c, const unsigned* a, const unsigned* b) {
    asm volatile(
        "mma.sync.aligned.m16n8k16.row.col.f32.f16.f16.f32 "
        "{%0,%1,%2,%3},{%4,%5,%6,%7},{%8,%9},{%0,%1,%2,%3};"
        : "+f"(c[0]), "+f"(c[1]), "+f"(c[2]), "+f"(c[3])
        : "r"(a[0]), "r"(a[1]), "r"(a[2]), "r"(a[3]), "r"(b[0]), "r"(b[1]));
}

// smem tile word index: 128 rows x 32 halfs (16 words). chunk = 4 words (16B).
// phys chunk = c ^ ((row>>1)&3)  -> conflict-free frag reads + cp.async stores
__device__ __forceinline__ int sw_idx(int row, int chunk, int w) {
    return row * 16 + ((chunk ^ ((row >> 1) & 3)) << 2) + w;
}

__device__ __forceinline__ void cp16(unsigned dst, const void* src) {
    asm volatile("cp.async.cg.shared.global [%0], [%1], 16;" :: "r"(dst), "l"(src));
}
__device__ __forceinline__ void cp_commit() { asm volatile("cp.async.commit_group;"); }
template<int N>
__device__ __forceinline__ void cp_wait() { asm volatile("cp.async.wait_group %0;" :: "n"(N)); }

// ---------------- embedding ----------------
__global__ void embed_kernel(const int* __restrict__ idx,
                             const float* __restrict__ tok,
                             const float* __restrict__ pos) {
    int bt = blockIdx.x;
    long long row = (long long)idx[bt];
    int t = bt % TT;
    const float* te = tok + row * DD;
    const float* pe = pos + (long long)t * DD;
    float* xo = g_x + (long long)bt * DD;
    for (int d = threadIdx.x; d < DD; d += blockDim.x)
        xo[d] = te[d] + pe[d];
}

// ---------------- pack wq/wk/wv -> transposed fp16 [L][3D][D] ----------------
__global__ void pack_qkv(const float* __restrict__ wq,
                         const float* __restrict__ wk,
                         const float* __restrict__ wv) {
    const long long total = (long long)LL * 3 * DD * DD;
    for (long long j = (long long)blockIdx.x * blockDim.x + threadIdx.x;
         j < total; j += (long long)gridDim.x * blockDim.x) {
        int l = (int)(j / ((long long)3 * DD * DD));
        long long r = j % ((long long)3 * DD * DD);
        int c = (int)(r / DD);          // output col 0..3D-1
        int d = (int)(r % DD);          // k index
        int m = c / DD;
        int c2 = c % DD;
        int h = c2 / HDD;
        int hd = c2 % HDD;
        const float* src = (m == 0) ? wq : ((m == 1) ? wk : wv);
        g_wqkvT[j] = __float2half(src[(((long long)l * HH + h) * DD + d) * HDD + hd]);
    }
}

// ---------------- transpose + cvt fp32 [R][C] -> fp16 [C][R], batched ------
__global__ void transpose_cvt(const float* __restrict__ src, __half* __restrict__ dst,
                              int R, int C) {
    __shared__ float s[32][33];
    const float* sp = src + (size_t)blockIdx.z * R * C;
    __half* dp = dst + (size_t)blockIdx.z * R * C;
    int tx = threadIdx.x, ty = threadIdx.y;
    int r0 = blockIdx.y * 32, c0 = blockIdx.x * 32;
    #pragma unroll
    for (int i = 0; i < 4; i++) {
        int r = r0 + ty + i * 8;
        s[ty + i * 8][tx] = sp[(long long)r * C + c0 + tx];
    }
    __syncthreads();
    #pragma unroll
    for (int i = 0; i < 4; i++) {
        int c = c0 + ty + i * 8;
        dp[(long long)c * R + r0 + tx] = __float2half(s[tx][ty + i * 8]);
    }
}

// ---------------- V transpose per layer: qkv -> vT [bh][128(pad)][T] -------
__global__ void v_transpose() {
    __shared__ __half s[32][33];
    int z = blockIdx.z;                 // b*H + h
    int b = z / HH, h = z % HH;
    int t0 = blockIdx.x * 32;
    int d0 = blockIdx.y * 32;
    int tx = threadIdx.x, ty = threadIdx.y;
    const __half* v = g_qkv + (long long)b * TT * 3 * DD + 2 * DD + h * HDD;
    #pragma unroll
    for (int i = 0; i < 4; i++) {
        int t = t0 + ty + i * 8;
        s[ty + i * 8][tx] = v[(long long)t * 3 * DD + d0 + tx];
    }
    __syncthreads();
    __half* o = g_vT + (long long)z * 128 * TT;
    #pragma unroll
    for (int i = 0; i < 4; i++) {
        int d = d0 + ty + i * 8;
        o[(long long)d * TT + t0 + tx] = s[tx][ty + i * 8];
    }
}

// ---------------- layernorm (fp32 in, fp16 out) ----------------
__global__ void ln_kernel(const float* __restrict__ in,
                          const float* __restrict__ g,
                          const float* __restrict__ b,
                          __half* __restrict__ out) {
    int row = blockIdx.x;
    const float* x = in + (long long)row * DD;
    __shared__ float rs[256];
    __shared__ float rs2[256];
    float s = 0.f, s2 = 0.f;
    for (int d = threadIdx.x; d < DD; d += 256) {
        float v = x[d];
        s += v; s2 += v * v;
    }
    rs[threadIdx.x] = s; rs2[threadIdx.x] = s2;
    __syncthreads();
    for (int o = 128; o > 0; o >>= 1) {
        if (threadIdx.x < o) { rs[threadIdx.x] += rs[threadIdx.x + o]; rs2[threadIdx.x] += rs2[threadIdx.x + o]; }
        __syncthreads();
    }
    float mean = rs[0] * (1.0f / DD);
    float var  = rs2[0] * (1.0f / DD) - mean * mean;
    float rstd = rsqrtf(var + 1e-5f);
    __half* o = out + (long long)row * DD;
    for (int d = threadIdx.x; d < DD; d += 256)
        o[d] = __float2half((x[d] - mean) * rstd * g[d] + b[d]);
}

// ---------------- causal scaled softmax: fp32 scores -> fp16 probs ---------
__global__ void softmax_kernel() {
    int r = blockIdx.x;
    int t = r % TT;
    const float* row = g_scores + (long long)r * TT;
    __half* prow = g_p + (long long)r * TT;
    __shared__ float red[256];
    const float scale = 0.125f;
    const int wlim = ((t >> 7) + 1) << 7;    // PV reads s < wlim only
    float vals[4];
    float mx = -1e30f;
    #pragma unroll
    for (int i = 0; i < 4; i++) {
        int s = threadIdx.x + i * 256;
        float v = (s <= t) ? row[s] * scale : -1e30f;
        vals[i] = v;
        mx = fmaxf(mx, v);
    }
    red[threadIdx.x] = mx; __syncthreads();
    for (int o = 128; o > 0; o >>= 1) {
        if (threadIdx.x < o) red[threadIdx.x] = fmaxf(red[threadIdx.x], red[threadIdx.x + o]);
        __syncthreads();
    }
    float m = red[0];
    __syncthreads();
    float sum = 0.f;
    #pragma unroll
    for (int i = 0; i < 4; i++) {
        float e = expf(vals[i] - m);
        vals[i] = e;
        sum += e;
    }
    red[threadIdx.x] = sum; __syncthreads();
    for (int o = 128; o > 0; o >>= 1) {
        if (threadIdx.x < o) red[threadIdx.x] += red[threadIdx.x + o];
        __syncthreads();
    }
    float inv = 1.0f / red[0];
    #pragma unroll
    for (int i = 0; i < 4; i++) {
        int s = threadIdx.x + i * 256;
        if (s < wlim) prow[s] = __float2half(vals[i] * inv);
    }
}

// ---------------- elementwise add: x = sa + ff2 ----------------
__global__ void add_kernel() {
    int n = BT * DD;
    for (int i = blockIdx.x * blockDim.x + threadIdx.x; i < n;
         i += gridDim.x * blockDim.x)
        g_x[i] = g_sa[i] + g_ff2[i];
}

// ---------------- fp16 tensor-core GEMM, cp.async pipelined ----------------
// C[M,N] = A[M,K] @ B^T  where A fp16 row-major [M,K] (lda), B fp16 [N,K] (ldb).
// 128 threads, 2x2 warps of 64x64. BK=32 (2 x k16 steps).
// EPI: 0 none, 1 +bias, 2 +bias+relu. OUTH: fp16 output else fp32.
// CSKIP: skip causal tiles. CCLIP: clip K to bm+BM.
template<int EPI, bool OUTH, bool CSKIP, bool CCLIP>
__global__ void __launch_bounds__(128, 2)
mma_gemm(const __half* __restrict__ A, const __half* __restrict__ B,
         const float* __restrict__ bias, void* __restrict__ Cv,
         int M, int N, int K, int lda, int ldb, int ldc,
         long long Ab, long long Ah, long long Bb, long long Bh,
         long long Cb, long long Ch, int HB) {
    __shared__ __align__(16) unsigned As[2][BM * 16];   // 128 rows x 32 halfs
    __shared__ __align__(16) unsigned Bs[2][BN * 16];

    const int zb = blockIdx.z / HB;
    const int zh = blockIdx.z % HB;
    A += zb * Ab + zh * Ah;
    B += zb * Bb + zh * Bh;

    const int bm = blockIdx.x * BM;
    const int bn = blockIdx.y * BN;
    if (CSKIP && bn >= bm + BM) return;

    const int Kend = CCLIP ? min(K, bm + BM) : K;
    const int nIter = Kend / BK;

    const int tid  = threadIdx.x;
    const int warp = tid >> 5;
    const int lane = tid & 31;
    const int g    = lane >> 2;
    const int tig  = lane & 3;
    const int wm   = (warp & 1) * 64;
    const int wn   = (warp >> 1) * 64;

    const unsigned sA = (unsigned)__cvta_generic_to_shared(&As[0][0]);
    const unsigned sB = (unsigned)__cvta_generic_to_shared(&Bs[0][0]);

    const int l_r = tid >> 2;        // 0..31 (+p*32)
    const int l_c = tid & 3;         // 16B chunk (8 halfs)

    auto issueLoads = [&](int stage, int k0) {
        #pragma unroll
        for (int p = 0; p < 4; p++) {
            int r = p * 32 + l_r;
            unsigned dst = sA + (unsigned)((stage * BM * 16 + sw_idx(r, l_c, 0)) * 4);
            cp16(dst, A + (long long)(bm + r) * lda + (k0 + l_c * 8));
        }
        #pragma unroll
        for (int p = 0; p < 4; p++) {
            int r = p * 32 + l_r;
            unsigned dst = sB + (unsigned)((stage * BN * 16 + sw_idx(r, l_c, 0)) * 4);
            cp16(dst, B + (long long)(bn + r) * ldb + (k0 + l_c * 8));
        }
    };

    float acc[4][8][4];
    #pragma unroll
    for (int i = 0; i < 4; i++)
        #pragma unroll
        for (int j = 0; j < 8; j++)
            #pragma unroll
            for (int q = 0; q < 4; q++) acc[i][j][q] = 0.f;

    // A frag (m16n8k16): a0=(g,2t),a1=(g+8,2t),a2=(g,2t+8),a3=(g+8,2t+8) as half2
    auto loadAfrag = [&](int buf, int ks, unsigned (*af)[4]) {
        #pragma unroll
        for (int mi = 0; mi < 4; mi++) {
            int m0 = wm + mi * 16 + g;
            af[mi][0] = As[buf][sw_idx(m0,     ks * 2,     tig)];
            af[mi][1] = As[buf][sw_idx(m0 + 8, ks * 2,     tig)];
            af[mi][2] = As[buf][sw_idx(m0,     ks * 2 + 1, tig)];
            af[mi][3] = As[buf][sw_idx(m0 + 8, ks * 2 + 1, tig)];
        }
    };
    // B frag: b0=(2t..2t+1, g), b1=(2t+8.., g) ; Bs is [n][k]
    auto loadBfrag = [&](int buf, int ks, int nj, unsigned& b0, unsigned& b1) {
        int n0 = wn + nj * 8 + g;
        b0 = Bs[buf][sw_idx(n0, ks * 2,     tig)];
        b1 = Bs[buf][sw_idx(n0, ks * 2 + 1, tig)];
    };

    issueLoads(0, 0);
    cp_commit();

    unsigned af[2][4][4];

    for (int it = 0; it < nIter; it++) {
        int buf = it & 1;
        if (it + 1 < nIter) {
            issueLoads(buf ^ 1, (it + 1) * BK);
            cp_commit();
            cp_wait<1>();
        } else {
            cp_wait<0>();
        }
        __syncthreads();

        loadAfrag(buf, 0, af[0]);
        #pragma unroll
        for (int ks = 0; ks < 2; ks++) {
            if (ks == 0) loadAfrag(buf, 1, af[1]);
            unsigned bc0, bc1, bn0, bn1;
            loadBfrag(buf, ks, 0, bc0, bc1);
            #pragma unroll
            for (int nj = 0; nj < 8; nj++) {
                if (nj < 7) loadBfrag(buf, ks, nj + 1, bn0, bn1);
                unsigned bb[2] = {bc0, bc1};
                #pragma unroll
                for (int mi = 0; mi < 4; mi++)
                    mma_f16(acc[mi][nj], af[ks][mi], bb);
                bc0 = bn0; bc1 = bn1;
            }
        }
        __syncthreads();
    }

    // epilogue
    #pragma unroll
    for (int mi = 0; mi < 4; mi++) {
        int row = bm + wm + mi * 16 + g;
        #pragma unroll
        for (int nj = 0; nj < 8; nj++) {
            int col = bn + wn + nj * 8 + tig * 2;
            if (col >= N) continue;
            float v0 = acc[mi][nj][0];
            float v1 = acc[mi][nj][1];
            float v2 = acc[mi][nj][2];
            float v3 = acc[mi][nj][3];
            if (EPI >= 1) {
                float bb0 = bias[col];
                float bb1 = bias[col + 1];
                v0 += bb0; v1 += bb1; v2 += bb0; v3 += bb1;
            }
            if (EPI == 2) {
                v0 = fmaxf(v0, 0.f); v1 = fmaxf(v1, 0.f);
                v2 = fmaxf(v2, 0.f); v3 = fmaxf(v3, 0.f);
            }
            if (OUTH) {
                __half* C = (__half*)Cv + zb * Cb + zh * Ch;
                *reinterpret_cast<__half2*>(C + (long long)row * ldc + col) =
                    __floats2half2_rn(v0, v1);
                *reinterpret_cast<__half2*>(C + (long long)(row + 8) * ldc + col) =
                    __floats2half2_rn(v2, v3);
            } else {
                float* C = (float*)Cv + zb * Cb + zh * Ch;
                *reinterpret_cast<float2*>(C + (long long)row * ldc + col)       = make_float2(v0, v1);
                *reinterpret_cast<float2*>(C + (long long)(row + 8) * ldc + col) = make_float2(v2, v3);
            }
        }
    }
}

extern "C" void kernel_launch(void* const* d_in, const int* in_sizes, int n_in,
                              void* d_out, int out_size) {
    const int*   idx     = (const int*)d_in[0];
    const float* tok_emb = (const float*)d_in[1];
    const float* pos_emb = (const float*)d_in[2];
    const float* wq      = (const float*)d_in[3];
    const float* wk      = (const float*)d_in[4];
    const float* wv      = (const float*)d_in[5];
    const float* w_proj  = (const float*)d_in[6];
    const float* b_proj  = (const float*)d_in[7];
    const float* w1      = (const float*)d_in[8];
    const float* b1      = (const float*)d_in[9];
    const float* w2      = (const float*)d_in[10];
    const float* b2      = (const float*)d_in[11];
    const float* ln1_g   = (const float*)d_in[12];
    const float* ln1_b   = (const float*)d_in[13];
    const float* ln2_g   = (const float*)d_in[14];
    const float* ln2_b   = (const float*)d_in[15];
    const float* lnf_g   = (const float*)d_in[16];
    const float* lnf_b   = (const float*)d_in[17];
    const float* w_lm    = (const float*)d_in[18];
    const float* b_lm    = (const float*)d_in[19];
    float* out = (float*)d_out;

    float  *px, *psa, *pff2, *pscores;
    __half *ph, *pqkv, *pattn, *pff1, *pp, *pvT;
    __half *pwqkvT, *pwprojT, *pw1T, *pw2T, *pwlmT;
    cudaGetSymbolAddress((void**)&px,      g_x);
    cudaGetSymbolAddress((void**)&ph,      g_h);
    cudaGetSymbolAddress((void**)&pqkv,    g_qkv);
    cudaGetSymbolAddress((void**)&pattn,   g_attn);
    cudaGetSymbolAddress((void**)&psa,     g_sa);
    cudaGetSymbolAddress((void**)&pff1,    g_ff1);
    cudaGetSymbolAddress((void**)&pff2,    g_ff2);
    cudaGetSymbolAddress((void**)&pscores, g_scores);
    cudaGetSymbolAddress((void**)&pp,      g_p);
    cudaGetSymbolAddress((void**)&pvT,     g_vT);
    cudaGetSymbolAddress((void**)&pwqkvT,  g_wqkvT);
    cudaGetSymbolAddress((void**)&pwprojT, g_wprojT);
    cudaGetSymbolAddress((void**)&pw1T,    g_w1T);
    cudaGetSymbolAddress((void**)&pw2T,    g_w2T);
    cudaGetSymbolAddress((void**)&pwlmT,   g_wlmT);

    // ---- weight prep: transpose + fp16 cvt ----
    pack_qkv<<<4096, 256>>>(wq, wk, wv);
    {
        dim3 th(32, 8);
        transpose_cvt<<<dim3(DD/32,  DD/32,  LL), th>>>(w_proj, pwprojT, DD,  DD);
        transpose_cvt<<<dim3(FFD/32, DD/32,  LL), th>>>(w1,     pw1T,    DD,  FFD);
        transpose_cvt<<<dim3(DD/32,  FFD/32, LL), th>>>(w2,     pw2T,    FFD, DD);
        transpose_cvt<<<dim3(VV/32,  DD/32,  1),  th>>>(w_lm,   pwlmT,   DD,  VV);
    }
    embed_kernel<<<BT, 256>>>(idx, tok_emb, pos_emb);

    const long long TT2 = (long long)TT * TT;

    for (int l = 0; l < LL; l++) {
        ln_kernel<<<BT, 256>>>(px, ln1_g + (long long)l*DD, ln1_b + (long long)l*DD, ph);

        // qkv = h @ wqkvT^T  -> fp16
        mma_gemm<0,true,false,false><<<dim3(BT/BM, 3*DD/BN, 1), 128>>>(
            ph, pwqkvT + (long long)l*3*DD*DD, nullptr, pqkv,
            BT, 3*DD, DD, DD, DD, 3*DD, 0,0,0,0,0,0, 1);

        // vT per head
        v_transpose<<<dim3(TT/32, HDD/32, BB*HH), dim3(32, 8)>>>();

        // scores = Q @ K^T -> fp32, causal skip
        mma_gemm<0,false,true,false><<<dim3(TT/BM, TT/BN, BB*HH), 128>>>(
            pqkv, pqkv + DD, nullptr, pscores,
            TT, TT, HDD,
            3*DD, 3*DD, TT,
            (long long)TT*3*DD, HDD,
            (long long)TT*3*DD, HDD,
            (long long)HH*TT2, TT2,
            HH);

        softmax_kernel<<<BB*HH*TT, 256>>>();

        // attn = P @ V -> fp16, K clipped
        mma_gemm<0,true,false,true><<<dim3(TT/BM, 1, BB*HH), 128>>>(
            pp, pvT, nullptr, pattn,
            TT, HDD, TT,
            TT, TT, DD,
            (long long)HH*TT2, TT2,
            (long long)HH*128*TT, (long long)128*TT,
            (long long)TT*DD, HDD,
            HH);

        // sa = attn @ w_proj + b_proj -> fp32
        mma_gemm<1,false,false,false><<<dim3(BT/BM, DD/BN, 1), 128>>>(
            pattn, pwprojT + (long long)l*DD*DD, b_proj + (long long)l*DD, psa,
            BT, DD, DD, DD, DD, DD, 0,0,0,0,0,0, 1);

        ln_kernel<<<BT, 256>>>(px, ln2_g + (long long)l*DD, ln2_b + (long long)l*DD, ph);

        // ff1 = relu(h @ w1 + b1) -> fp16
        mma_gemm<2,true,false,false><<<dim3(BT/BM, FFD/BN, 1), 128>>>(
            ph, pw1T + (long long)l*FFD*DD, b1 + (long long)l*FFD, pff1,
            BT, FFD, DD, DD, DD, FFD, 0,0,0,0,0,0, 1);

        // ff2 = ff1 @ w2 + b2 -> fp32
        mma_gemm<1,false,false,false><<<dim3(BT/BM, DD/BN, 1), 128>>>(
            pff1, pw2T + (long long)l*DD*FFD, b2 + (long long)l*DD, pff2,
            BT, DD, FFD, FFD, FFD, DD, 0,0,0,0,0,0, 1);

        add_kernel<<<2048, 256>>>();
    }

    ln_kernel<<<BT, 256>>>(px, lnf_g, lnf_b, ph);

    // logits = h @ w_lm + b_lm -> fp32
    mma_gemm<1,false,false,false><<<dim3(BT/BM, VV/BN, 1), 128>>>(
        ph, pwlmT, b_lm, out,
        BT, VV, DD, DD, DD, VV, 0,0,0,0,0,0, 1);
}

// round 9
// speedup vs baseline: 2.3250x; 1.0551x over previous
#include <cuda_runtime.h>
#include <cuda_fp16.h>
#include <math.h>

// Problem constants
#define BB  2
#define TT  1024
#define DD  1024
#define HH  16
#define HDD 64
#define LL  3
#define VV  32000
#define FFD 4096
#define BT  (BB*TT)

#define BM 128
#define BN 128
#define BK 32
#define NS 3            // cp.async pipeline stages

// ---------------- static scratch (allocation-free) ----------------
__device__ float  g_x   [BT*DD];                       // fp32 residual stream
__device__ __half g_h   [BT*DD];                       // LN output
__device__ __half g_qkv [BT*3*DD];
__device__ __half g_attn[BT*DD];
__device__ float  g_sa  [BT*DD];
__device__ __half g_ff1 [(size_t)BT*FFD];
__device__ float  g_scores[(size_t)BB*HH*TT*TT];       // 128 MB fp32
__device__ __half g_p   [(size_t)BB*HH*TT*TT];         // softmax probs fp16
__device__ __half g_vT  [(size_t)BB*HH*128*TT];        // V transposed, padded
// fp16 transposed weights
__device__ __half g_wqkvT [(size_t)LL*3*DD*DD];        // [l][n=3D][k=D]
__device__ __half g_wprojT[(size_t)LL*DD*DD];
__device__ __half g_w1T   [(size_t)LL*FFD*DD];
__device__ __half g_w2T   [(size_t)LL*DD*FFD];
__device__ __half g_wlmT  [(size_t)VV*DD];

// ---------------- helpers ----------------
__device__ __forceinline__ void mma_f16(float* c, const unsigned* a, const unsigned* b) {
    asm volatile(
        "mma.sync.aligned.m16n8k16.row.col.f32.f16.f16.f32 "
        "{%0,%1,%2,%3},{%4,%5,%6,%7},{%8,%9},{%0,%1,%2,%3};"
        : "+f"(c[0]), "+f"(c[1]), "+f"(c[2]), "+f"(c[3])
        : "r"(a[0]), "r"(a[1]), "r"(a[2]), "r"(a[3]), "r"(b[0]), "r"(b[1]));
}

// smem tile word index: 128 rows x 32 halfs (16 words). chunk = 4 words (16B).
// phys chunk = c ^ ((row>>1)&3)  -> conflict-free frag reads + cp.async stores
__device__ __forceinline__ int sw_idx(int row, int chunk, int w) {
    return row * 16 + ((chunk ^ ((row >> 1) & 3)) << 2) + w;
}

__device__ __forceinline__ void cp16(unsigned dst, const void* src) {
    asm volatile("cp.async.cg.shared.global [%0], [%1], 16;" :: "r"(dst), "l"(src));
}
__device__ __forceinline__ void cp_commit() { asm volatile("cp.async.commit_group;"); }
template<int N>
__device__ __forceinline__ void cp_wait() { asm volatile("cp.async.wait_group %0;" :: "n"(N)); }

// ---------------- embedding ----------------
__global__ void embed_kernel(const int* __restrict__ idx,
                             const float* __restrict__ tok,
                             const float* __restrict__ pos) {
    int bt = blockIdx.x;
    long long row = (long long)idx[bt];
    int t = bt % TT;
    const float* te = tok + row * DD;
    const float* pe = pos + (long long)t * DD;
    float* xo = g_x + (long long)bt * DD;
    for (int d = threadIdx.x; d < DD; d += blockDim.x)
        xo[d] = te[d] + pe[d];
}

// ---------------- pack wq/wk/wv -> transposed fp16 [L][3D][D] (coalesced) --
// One launch per matrix m. Each z = l*HH + h handles a [D][HD] -> [HD][D]
// transpose. GRID: x covers hd (HDD/32), y covers d (DD/32).
__global__ void pack_qkv_t(const float* __restrict__ src, int m) {
    __shared__ float s[32][33];
    int z = blockIdx.z;
    int l = z / HH, h = z % HH;
    const float* sp = src + (long long)z * DD * HDD;
    __half* dp = g_wqkvT + ((long long)(l * 3 + m) * DD + h * HDD) * DD;
    int tx = threadIdx.x, ty = threadIdx.y;
    int r0 = blockIdx.y * 32, c0 = blockIdx.x * 32;   // r: d index (0..D), c: hd index (0..HD)
    #pragma unroll
    for (int i = 0; i < 4; i++) {
        int r = r0 + ty + i * 8;
        s[ty + i * 8][tx] = sp[(long long)r * HDD + c0 + tx];
    }
    __syncthreads();
    #pragma unroll
    for (int i = 0; i < 4; i++) {
        int c = c0 + ty + i * 8;
        dp[(long long)c * DD + r0 + tx] = __float2half(s[tx][ty + i * 8]);
    }
}

// ---------------- transpose + cvt fp32 [R][C] -> fp16 [C][R], batched ------
__global__ void transpose_cvt(const float* __restrict__ src, __half* __restrict__ dst,
                              int R, int C) {
    __shared__ float s[32][33];
    const float* sp = src + (size_t)blockIdx.z * R * C;
    __half* dp = dst + (size_t)blockIdx.z * R * C;
    int tx = threadIdx.x, ty = threadIdx.y;
    int r0 = blockIdx.y * 32, c0 = blockIdx.x * 32;
    #pragma unroll
    for (int i = 0; i < 4; i++) {
        int r = r0 + ty + i * 8;
        s[ty + i * 8][tx] = sp[(long long)r * C + c0 + tx];
    }
    __syncthreads();
    #pragma unroll
    for (int i = 0; i < 4; i++) {
        int c = c0 + ty + i * 8;
        dp[(long long)c * R + r0 + tx] = __float2half(s[tx][ty + i * 8]);
    }
}

// ---------------- V transpose per layer: qkv -> vT [bh][128(pad)][T] -------
__global__ void v_transpose() {
    __shared__ __half s[32][33];
    int z = blockIdx.z;                 // b*H + h
    int b = z / HH, h = z % HH;
    int t0 = blockIdx.x * 32;
    int d0 = blockIdx.y * 32;
    int tx = threadIdx.x, ty = threadIdx.y;
    const __half* v = g_qkv + (long long)b * TT * 3 * DD + 2 * DD + h * HDD;
    #pragma unroll
    for (int i = 0; i < 4; i++) {
        int t = t0 + ty + i * 8;
        s[ty + i * 8][tx] = v[(long long)t * 3 * DD + d0 + tx];
    }
    __syncthreads();
    __half* o = g_vT + (long long)z * 128 * TT;
    #pragma unroll
    for (int i = 0; i < 4; i++) {
        int d = d0 + ty + i * 8;
        o[(long long)d * TT + t0 + tx] = s[tx][ty + i * 8];
    }
}

// ---------------- layernorm (fp32 in, fp16 out) ----------------
__global__ void ln_kernel(const float* __restrict__ in,
                          const float* __restrict__ g,
                          const float* __restrict__ b,
                          __half* __restrict__ out) {
    int row = blockIdx.x;
    const float* x = in + (long long)row * DD;
    __shared__ float rs[256];
    __shared__ float rs2[256];
    float s = 0.f, s2 = 0.f;
    for (int d = threadIdx.x; d < DD; d += 256) {
        float v = x[d];
        s += v; s2 += v * v;
    }
    rs[threadIdx.x] = s; rs2[threadIdx.x] = s2;
    __syncthreads();
    for (int o = 128; o > 0; o >>= 1) {
        if (threadIdx.x < o) { rs[threadIdx.x] += rs[threadIdx.x + o]; rs2[threadIdx.x] += rs2[threadIdx.x + o]; }
        __syncthreads();
    }
    float mean = rs[0] * (1.0f / DD);
    float var  = rs2[0] * (1.0f / DD) - mean * mean;
    float rstd = rsqrtf(var + 1e-5f);
    __half* o = out + (long long)row * DD;
    for (int d = threadIdx.x; d < DD; d += 256)
        o[d] = __float2half((x[d] - mean) * rstd * g[d] + b[d]);
}

// ---------------- causal scaled softmax: fp32 scores -> fp16 probs ---------
__global__ void softmax_kernel() {
    int r = blockIdx.x;
    int t = r % TT;
    const float* row = g_scores + (long long)r * TT;
    __half* prow = g_p + (long long)r * TT;
    __shared__ float red[256];
    const float scale = 0.125f;
    const int wlim = ((t >> 7) + 1) << 7;    // PV reads s < wlim only
    float vals[4];
    float mx = -1e30f;
    #pragma unroll
    for (int i = 0; i < 4; i++) {
        int s = threadIdx.x + i * 256;
        float v = (s <= t) ? row[s] * scale : -1e30f;
        vals[i] = v;
        mx = fmaxf(mx, v);
    }
    red[threadIdx.x] = mx; __syncthreads();
    for (int o = 128; o > 0; o >>= 1) {
        if (threadIdx.x < o) red[threadIdx.x] = fmaxf(red[threadIdx.x], red[threadIdx.x + o]);
        __syncthreads();
    }
    float m = red[0];
    __syncthreads();
    float sum = 0.f;
    #pragma unroll
    for (int i = 0; i < 4; i++) {
        float e = expf(vals[i] - m);
        vals[i] = e;
        sum += e;
    }
    red[threadIdx.x] = sum; __syncthreads();
    for (int o = 128; o > 0; o >>= 1) {
        if (threadIdx.x < o) red[threadIdx.x] += red[threadIdx.x + o];
        __syncthreads();
    }
    float inv = 1.0f / red[0];
    #pragma unroll
    for (int i = 0; i < 4; i++) {
        int s = threadIdx.x + i * 256;
        if (s < wlim) prow[s] = __float2half(vals[i] * inv);
    }
}

// ---------------- fp16 tensor-core GEMM, 3-stage cp.async ----------------
// C[M,N] = A[M,K] @ B^T, A fp16 row-major [M,K] (lda), B fp16 [N,K] (ldb).
// 128 threads, 2x2 warps of 64x64, BK=32.
// EPI: 0 none, 1 +bias, 2 +bias+relu, 3 +bias +aux (residual fuse).
// OUTH: fp16 out else fp32. CSKIP: causal skip. CCLIP: clip K to bm+BM.
template<int EPI, bool OUTH, bool CSKIP, bool CCLIP>
__global__ void __launch_bounds__(128, 2)
mma_gemm(const __half* __restrict__ A, const __half* __restrict__ B,
         const float* __restrict__ bias, const float* __restrict__ aux,
         void* __restrict__ Cv,
         int M, int N, int K, int lda, int ldb, int ldc,
         long long Ab, long long Ah, long long Bb, long long Bh,
         long long Cb, long long Ch, int HB) {
    __shared__ __align__(16) unsigned As[NS][BM * 16];   // 3 x 8 KB
    __shared__ __align__(16) unsigned Bs[NS][BN * 16];   // 3 x 8 KB  (total 48 KB)

    const int zb = blockIdx.z / HB;
    const int zh = blockIdx.z % HB;
    A += zb * Ab + zh * Ah;
    B += zb * Bb + zh * Bh;

    const int bm = blockIdx.x * BM;
    const int bn = blockIdx.y * BN;
    if (CSKIP && bn >= bm + BM) return;

    const int Kend = CCLIP ? min(K, bm + BM) : K;
    const int nIter = Kend / BK;

    const int tid  = threadIdx.x;
    const int warp = tid >> 5;
    const int lane = tid & 31;
    const int g    = lane >> 2;
    const int tig  = lane & 3;
    const int wm   = (warp & 1) * 64;
    const int wn   = (warp >> 1) * 64;

    const unsigned sA = (unsigned)__cvta_generic_to_shared(&As[0][0]);
    const unsigned sB = (unsigned)__cvta_generic_to_shared(&Bs[0][0]);

    const int l_r = tid >> 2;        // 0..31 (+p*32)
    const int l_c = tid & 3;         // 16B chunk (8 halfs)

    auto issueLoads = [&](int stage, int k0) {
        #pragma unroll
        for (int p = 0; p < 4; p++) {
            int r = p * 32 + l_r;
            unsigned dst = sA + (unsigned)((stage * BM * 16 + sw_idx(r, l_c, 0)) * 4);
            cp16(dst, A + (long long)(bm + r) * lda + (k0 + l_c * 8));
        }
        #pragma unroll
        for (int p = 0; p < 4; p++) {
            int r = p * 32 + l_r;
            unsigned dst = sB + (unsigned)((stage * BN * 16 + sw_idx(r, l_c, 0)) * 4);
            cp16(dst, B + (long long)(bn + r) * ldb + (k0 + l_c * 8));
        }
    };

    float acc[4][8][4];
    #pragma unroll
    for (int i = 0; i < 4; i++)
        #pragma unroll
        for (int j = 0; j < 8; j++)
            #pragma unroll
            for (int q = 0; q < 4; q++) acc[i][j][q] = 0.f;

    auto loadAfrag = [&](int buf, int ks, unsigned (*af)[4]) {
        #pragma unroll
        for (int mi = 0; mi < 4; mi++) {
            int m0 = wm + mi * 16 + g;
            af[mi][0] = As[buf][sw_idx(m0,     ks * 2,     tig)];
            af[mi][1] = As[buf][sw_idx(m0 + 8, ks * 2,     tig)];
            af[mi][2] = As[buf][sw_idx(m0,     ks * 2 + 1, tig)];
            af[mi][3] = As[buf][sw_idx(m0 + 8, ks * 2 + 1, tig)];
        }
    };
    auto loadBfrag = [&](int buf, int ks, int nj, unsigned& b0, unsigned& b1) {
        int n0 = wn + nj * 8 + g;
        b0 = Bs[buf][sw_idx(n0, ks * 2,     tig)];
        b1 = Bs[buf][sw_idx(n0, ks * 2 + 1, tig)];
    };

    // prologue: fill stages 0,1
    issueLoads(0, 0);
    cp_commit();
    if (nIter > 1) { issueLoads(1, BK); cp_commit(); }

    unsigned af[2][4][4];

    for (int it = 0; it < nIter; it++) {
        int buf = it % NS;
        if (it + 2 < nIter) {
            issueLoads((it + 2) % NS, (it + 2) * BK);
            cp_commit();
            cp_wait<2>();
        } else if (it + 1 < nIter) {
            cp_wait<1>();
        } else {
            cp_wait<0>();
        }
        __syncthreads();

        loadAfrag(buf, 0, af[0]);
        #pragma unroll
        for (int ks = 0; ks < 2; ks++) {
            if (ks == 0) loadAfrag(buf, 1, af[1]);
            unsigned bc0, bc1, bn0, bn1;
            loadBfrag(buf, ks, 0, bc0, bc1);
            #pragma unroll
            for (int nj = 0; nj < 8; nj++) {
                if (nj < 7) loadBfrag(buf, ks, nj + 1, bn0, bn1);
                unsigned bb[2] = {bc0, bc1};
                #pragma unroll
                for (int mi = 0; mi < 4; mi++)
                    mma_f16(acc[mi][nj], af[ks][mi], bb);
                bc0 = bn0; bc1 = bn1;
            }
        }
        __syncthreads();
    }

    // epilogue
    #pragma unroll
    for (int mi = 0; mi < 4; mi++) {
        int row = bm + wm + mi * 16 + g;
        #pragma unroll
        for (int nj = 0; nj < 8; nj++) {
            int col = bn + wn + nj * 8 + tig * 2;
            if (col >= N) continue;
            float v0 = acc[mi][nj][0];
            float v1 = acc[mi][nj][1];
            float v2 = acc[mi][nj][2];
            float v3 = acc[mi][nj][3];
            if (EPI >= 1) {
                float bb0 = bias[col];
                float bb1 = bias[col + 1];
                v0 += bb0; v1 += bb1; v2 += bb0; v3 += bb1;
            }
            if (EPI == 2) {
                v0 = fmaxf(v0, 0.f); v1 = fmaxf(v1, 0.f);
                v2 = fmaxf(v2, 0.f); v3 = fmaxf(v3, 0.f);
            }
            if (EPI == 3) {
                float2 a0 = *reinterpret_cast<const float2*>(aux + (long long)row * ldc + col);
                float2 a1 = *reinterpret_cast<const float2*>(aux + (long long)(row + 8) * ldc + col);
                v0 += a0.x; v1 += a0.y; v2 += a1.x; v3 += a1.y;
            }
            if (OUTH) {
                __half* C = (__half*)Cv + zb * Cb + zh * Ch;
                *reinterpret_cast<__half2*>(C + (long long)row * ldc + col) =
                    __floats2half2_rn(v0, v1);
                *reinterpret_cast<__half2*>(C + (long long)(row + 8) * ldc + col) =
                    __floats2half2_rn(v2, v3);
            } else {
                float* C = (float*)Cv + zb * Cb + zh * Ch;
                *reinterpret_cast<float2*>(C + (long long)row * ldc + col)       = make_float2(v0, v1);
                *reinterpret_cast<float2*>(C + (long long)(row + 8) * ldc + col) = make_float2(v2, v3);
            }
        }
    }
}

extern "C" void kernel_launch(void* const* d_in, const int* in_sizes, int n_in,
                              void* d_out, int out_size) {
    const int*   idx     = (const int*)d_in[0];
    const float* tok_emb = (const float*)d_in[1];
    const float* pos_emb = (const float*)d_in[2];
    const float* wq      = (const float*)d_in[3];
    const float* wk      = (const float*)d_in[4];
    const float* wv      = (const float*)d_in[5];
    const float* w_proj  = (const float*)d_in[6];
    const float* b_proj  = (const float*)d_in[7];
    const float* w1      = (const float*)d_in[8];
    const float* b1      = (const float*)d_in[9];
    const float* w2      = (const float*)d_in[10];
    const float* b2      = (const float*)d_in[11];
    const float* ln1_g   = (const float*)d_in[12];
    const float* ln1_b   = (const float*)d_in[13];
    const float* ln2_g   = (const float*)d_in[14];
    const float* ln2_b   = (const float*)d_in[15];
    const float* lnf_g   = (const float*)d_in[16];
    const float* lnf_b   = (const float*)d_in[17];
    const float* w_lm    = (const float*)d_in[18];
    const float* b_lm    = (const float*)d_in[19];
    float* out = (float*)d_out;

    float  *px, *psa, *pscores;
    __half *ph, *pqkv, *pattn, *pff1, *pp, *pvT;
    __half *pwqkvT, *pwprojT, *pw1T, *pw2T, *pwlmT;
    cudaGetSymbolAddress((void**)&px,      g_x);
    cudaGetSymbolAddress((void**)&ph,      g_h);
    cudaGetSymbolAddress((void**)&pqkv,    g_qkv);
    cudaGetSymbolAddress((void**)&pattn,   g_attn);
    cudaGetSymbolAddress((void**)&psa,     g_sa);
    cudaGetSymbolAddress((void**)&pff1,    g_ff1);
    cudaGetSymbolAddress((void**)&pscores, g_scores);
    cudaGetSymbolAddress((void**)&pp,      g_p);
    cudaGetSymbolAddress((void**)&pvT,     g_vT);
    cudaGetSymbolAddress((void**)&pwqkvT,  g_wqkvT);
    cudaGetSymbolAddress((void**)&pwprojT, g_wprojT);
    cudaGetSymbolAddress((void**)&pw1T,    g_w1T);
    cudaGetSymbolAddress((void**)&pw2T,    g_w2T);
    cudaGetSymbolAddress((void**)&pwlmT,   g_wlmT);

    // ---- weight prep: transpose + fp16 cvt (all coalesced) ----
    {
        dim3 th(32, 8);
        // pack_qkv_t: x covers hd (HDD/32), y covers d (DD/32)
        pack_qkv_t<<<dim3(HDD/32, DD/32, LL*HH), th>>>(wq, 0);
        pack_qkv_t<<<dim3(HDD/32, DD/32, LL*HH), th>>>(wk, 1);
        pack_qkv_t<<<dim3(HDD/32, DD/32, LL*HH), th>>>(wv, 2);
        transpose_cvt<<<dim3(DD/32,  DD/32,  LL), th>>>(w_proj, pwprojT, DD,  DD);
        transpose_cvt<<<dim3(FFD/32, DD/32,  LL), th>>>(w1,     pw1T,    DD,  FFD);
        transpose_cvt<<<dim3(DD/32,  FFD/32, LL), th>>>(w2,     pw2T,    FFD, DD);
        transpose_cvt<<<dim3(VV/32,  DD/32,  1),  th>>>(w_lm,   pwlmT,   DD,  VV);
    }
    embed_kernel<<<BT, 256>>>(idx, tok_emb, pos_emb);

    const long long TT2 = (long long)TT * TT;

    for (int l = 0; l < LL; l++) {
        ln_kernel<<<BT, 256>>>(px, ln1_g + (long long)l*DD, ln1_b + (long long)l*DD, ph);

        // qkv = h @ wqkvT^T  -> fp16
        mma_gemm<0,true,false,false><<<dim3(BT/BM, 3*DD/BN, 1), 128>>>(
            ph, pwqkvT + (long long)l*3*DD*DD, nullptr, nullptr, pqkv,
            BT, 3*DD, DD, DD, DD, 3*DD, 0,0,0,0,0,0, 1);

        // vT per head
        v_transpose<<<dim3(TT/32, HDD/32, BB*HH), dim3(32, 8)>>>();

        // scores = Q @ K^T -> fp32, causal skip
        mma_gemm<0,false,true,false><<<dim3(TT/BM, TT/BN, BB*HH), 128>>>(
            pqkv, pqkv + DD, nullptr, nullptr, pscores,
            TT, TT, HDD,
            3*DD, 3*DD, TT,
            (long long)TT*3*DD, HDD,
            (long long)TT*3*DD, HDD,
            (long long)HH*TT2, TT2,
            HH);

        softmax_kernel<<<BB*HH*TT, 256>>>();

        // attn = P @ V -> fp16, K clipped
        mma_gemm<0,true,false,true><<<dim3(TT/BM, 1, BB*HH), 128>>>(
            pp, pvT, nullptr, nullptr, pattn,
            TT, HDD, TT,
            TT, TT, DD,
            (long long)HH*TT2, TT2,
            (long long)HH*128*TT, (long long)128*TT,
            (long long)TT*DD, HDD,
            HH);

        // sa = attn @ w_proj + b_proj -> fp32
        mma_gemm<1,false,false,false><<<dim3(BT/BM, DD/BN, 1), 128>>>(
            pattn, pwprojT + (long long)l*DD*DD, b_proj + (long long)l*DD, nullptr, psa,
            BT, DD, DD, DD, DD, DD, 0,0,0,0,0,0, 1);

        ln_kernel<<<BT, 256>>>(px, ln2_g + (long long)l*DD, ln2_b + (long long)l*DD, ph);

        // ff1 = relu(h @ w1 + b1) -> fp16
        mma_gemm<2,true,false,false><<<dim3(BT/BM, FFD/BN, 1), 128>>>(
            ph, pw1T + (long long)l*FFD*DD, b1 + (long long)l*FFD, nullptr, pff1,
            BT, FFD, DD, DD, DD, FFD, 0,0,0,0,0,0, 1);

        // x = ff1 @ w2 + b2 + sa  (residual fused) -> fp32
        mma_gemm<3,false,false,false><<<dim3(BT/BM, DD/BN, 1), 128>>>(
            pff1, pw2T + (long long)l*DD*FFD, b2 + (long long)l*DD, psa, px,
            BT, DD, FFD, FFD, FFD, DD, 0,0,0,0,0,0, 1);
    }

    ln_kernel<<<BT, 256>>>(px, lnf_g, lnf_b, ph);

    // logits = h @ w_lm + b_lm -> fp32
    mma_gemm<1,false,false,false><<<dim3(BT/BM, VV/BN, 1), 128>>>(
        ph, pwlmT, b_lm, nullptr, out,
        BT, VV, DD, DD, DD, VV, 0,0,0,0,0,0, 1);
}